// round 8
// baseline (speedup 1.0000x reference)
#include <cuda_runtime.h>
#include <math.h>

#define HW 65536
#define WID 256
#define HGT 256

// Scratch (no allocations allowed)
__device__ float g_h0[2 * 48 * HW];
__device__ float g_h1[2 * 48 * HW];
__device__ float g_ab[2 * 24 * HW];   // batch0 = a, batch1 = b
__device__ unsigned g_warr[60000];    // fragment-arranged tf32 weights

// ---- tf32 helpers ----------------------------------------------------------
__device__ __forceinline__ unsigned f2tf32(float f) {
    unsigned r;
    asm("cvt.rna.tf32.f32 %0, %1;" : "=r"(r) : "f"(f));
    return r;
}
__device__ __forceinline__ void mma_tf32(float c[4], const unsigned* a,
                                         unsigned b0, unsigned b1) {
    asm("mma.sync.aligned.m16n8k8.row.col.f32.tf32.tf32.f32 "
        "{%0,%1,%2,%3}, {%4,%5,%6,%7}, {%8,%9}, {%0,%1,%2,%3};"
        : "+f"(c[0]), "+f"(c[1]), "+f"(c[2]), "+f"(c[3])
        : "r"(a[0]), "r"(a[1]), "r"(a[2]), "r"(a[3]), "r"(b0), "r"(b1));
}

// ---------------------------------------------------------------------------
// Pre-arrange ALL conv weights into per-lane mma fragment order (one launch).
// Layout in g_warr: conv0 @0 (3456), conv1 @3456 (20736), conv2 @24192
// (20736), conv3 @44928 (13824).  Total 58752.
// ---------------------------------------------------------------------------
__global__ void arrange_all(const float* __restrict__ w0,
                            const float* __restrict__ w1,
                            const float* __restrict__ w2,
                            const float* __restrict__ w3,
                            unsigned* __restrict__ dst)
{
    int idx = blockIdx.x * 256 + threadIdx.x;
    if (idx >= 58752) return;
    const float* w;
    int CIN, COUT, KSTEPS, MF, base;
    if (idx < 3456)       { w = w0; CIN = 3;  COUT = 48; KSTEPS = 1; MF = 3; base = 0; }
    else if (idx < 24192) { w = w1; CIN = 48; COUT = 48; KSTEPS = 6; MF = 3; base = 3456; }
    else if (idx < 44928) { w = w2; CIN = 48; COUT = 48; KSTEPS = 6; MF = 3; base = 24192; }
    else                  { w = w3; CIN = 48; COUT = 24; KSTEPS = 6; MF = 2; base = 44928; }
    int i    = idx - base;
    int j    = i & 3;
    int lane = (i >> 2) & 31;
    int rest = i >> 7;               // (tap*KSTEPS+s)*MF+mf
    int mf   = rest % MF;
    int ts   = rest / MF;
    int s    = ts % KSTEPS;
    int tap  = ts / KSTEPS;
    int cout = 16 * mf + (lane >> 2) + ((j & 1) << 3);
    int ci   = 8 * s + (lane & 3) + ((j & 2) << 1);
    float v = (cout < COUT && ci < CIN) ? w[(cout * CIN + ci) * 9 + tap] : 0.f;
    dst[idx] = f2tf32(v);
}

// ---------------------------------------------------------------------------
// Tensor-core 3x3 conv (implicit GEMM, tf32 mma.sync).  (unchanged from R6)
// ---------------------------------------------------------------------------
template <int CIN, int CIN_STAGE, int COUT, int KSTEPS, int MF, int CIP, bool SKIP>
__global__ void __launch_bounds__(256, 2) conv_mma(
    const float* __restrict__ in, const unsigned* __restrict__ warr,
    const float* __restrict__ bias, float* __restrict__ out,
    long in_bs, long out_bs,
    const float* __restrict__ skip_in, const float* __restrict__ skip_w,
    const float* __restrict__ skip_b)
{
    extern __shared__ unsigned s_in[];   // [18*18][CIP] tf32
    const int tid = threadIdx.x;
    const int batch = blockIdx.z;
    in  += (long)batch * in_bs;
    out += (long)batch * out_bs;
    const int x0 = blockIdx.x * 16, y0 = blockIdx.y * 16;

    for (int idx = tid; idx < 324 * CIN_STAGE; idx += 256) {
        int ci = idx / 324, rc = idx % 324;
        int r = rc / 18, c = rc % 18;
        int gy = y0 - 1 + r, gx = x0 - 1 + c;
        float v = 0.f;
        if (ci < CIN && (unsigned)gy < HGT && (unsigned)gx < WID)
            v = in[(long)ci * HW + gy * WID + gx];
        s_in[rc * CIP + ci] = f2tf32(v);
    }
    __syncthreads();

    const int w = tid >> 5, lane = tid & 31;
    const int q = lane >> 2, t4 = lane & 3;

    float acc[MF][4][4];
#pragma unroll
    for (int mf = 0; mf < MF; mf++)
#pragma unroll
        for (int nf = 0; nf < 4; nf++)
#pragma unroll
            for (int j = 0; j < 4; j++) acc[mf][nf][j] = 0.f;

    int base[4];
#pragma unroll
    for (int nf = 0; nf < 4; nf++) {
        int yn = 2 * w + (nf >> 1);
        int xn = 8 * (nf & 1) + q;
        base[nf] = ((yn + 1) * 18 + (xn + 1)) * CIP + t4;
    }
    const uint4* wp = (const uint4*)warr + lane;

#pragma unroll
    for (int tap = 0; tap < 9; tap++) {
        const int dy = tap / 3 - 1, dx = tap % 3 - 1;
        const int off = (dy * 18 + dx) * CIP;
#pragma unroll
        for (int s = 0; s < KSTEPS; s++) {
            uint4 a[MF];
#pragma unroll
            for (int mf = 0; mf < MF; mf++)
                a[mf] = wp[((tap * KSTEPS + s) * MF + mf) * 32];
#pragma unroll
            for (int nf = 0; nf < 4; nf++) {
                int ad = base[nf] + off + 8 * s;
                unsigned b0 = s_in[ad];
                unsigned b1 = s_in[ad + 4];
#pragma unroll
                for (int mf = 0; mf < MF; mf++)
                    mma_tf32(acc[mf][nf], (const unsigned*)&a[mf], b0, b1);
            }
        }
    }

#pragma unroll
    for (int mf = 0; mf < MF; mf++) {
        const int coutL = 16 * mf + q;
        const int coutH = coutL + 8;
        const float bL = (coutL < COUT) ? __ldg(bias + coutL) : 0.f;
        const float bH = (coutH < COUT) ? __ldg(bias + coutH) : 0.f;
#pragma unroll
        for (int nf = 0; nf < 4; nf++) {
            const int gy = y0 + 2 * w + (nf >> 1);
            const int gx = x0 + 8 * (nf & 1) + 2 * t4;
            const int o = gy * WID + gx;
            float v0 = fmaxf(acc[mf][nf][0] + bL, 0.f);
            float v1 = fmaxf(acc[mf][nf][1] + bL, 0.f);
            float v2 = fmaxf(acc[mf][nf][2] + bH, 0.f);
            float v3 = fmaxf(acc[mf][nf][3] + bH, 0.f);
            if (SKIP) {
                const float* xp = skip_in + (long)batch * 3 * HW;
                float xa0 = __ldg(xp + o),          xb0 = __ldg(xp + o + 1);
                float xa1 = __ldg(xp + HW + o),     xb1 = __ldg(xp + HW + o + 1);
                float xa2 = __ldg(xp + 2 * HW + o), xb2 = __ldg(xp + 2 * HW + o + 1);
                if (coutL < COUT) {
                    float sb = __ldg(skip_b + coutL);
                    float w0 = __ldg(skip_w + coutL * 3);
                    float w1 = __ldg(skip_w + coutL * 3 + 1);
                    float w2 = __ldg(skip_w + coutL * 3 + 2);
                    v0 += sb + xa0 * w0 + xa1 * w1 + xa2 * w2;
                    v1 += sb + xb0 * w0 + xb1 * w1 + xb2 * w2;
                    *(float2*)(out + (long)coutL * HW + o) = make_float2(v0, v1);
                }
                if (coutH < COUT) {
                    float sb = __ldg(skip_b + coutH);
                    float w0 = __ldg(skip_w + coutH * 3);
                    float w1 = __ldg(skip_w + coutH * 3 + 1);
                    float w2 = __ldg(skip_w + coutH * 3 + 2);
                    v2 += sb + xa0 * w0 + xa1 * w1 + xa2 * w2;
                    v3 += sb + xb0 * w0 + xb1 * w1 + xb2 * w2;
                    *(float2*)(out + (long)coutH * HW + o) = make_float2(v2, v3);
                }
            } else {
                *(float2*)(out + (long)coutL * HW + o) = make_float2(v0, v1);
                *(float2*)(out + (long)coutH * HW + o) = make_float2(v2, v3);
            }
        }
    }
}

// ---------------------------------------------------------------------------
// Fused QKV + local 7x7 attention + residual + concat.
// CTA = 16x16 pixel tile, 256 threads (1 px/thread).
// Phase 1: stage 22x22 halo of `a` into smem (stride 25, OOB zero-filled).
// Phase 2: compute K tile into s_kv on the fly (OOB -> exact 0, matching
//          the zero-padded unfold). Scores need no bounds checks.
// Phase 3: per-thread scores + softmax in registers.
// Phase 4: overwrite s_kv with V tile; weighted sum.
// Epilogue: out[0:24] = y + a(center, from smem), out[24:48] = b (re-read).
// ---------------------------------------------------------------------------
#define TS 22
#define NPX 484           // 22*22
#define CST 25            // padded channel stride (gcd(25,32)=1 -> conflict-free)

__global__ void __launch_bounds__(256, 2) attn_fused(
    const float* __restrict__ a, const float* __restrict__ b,
    const float* __restrict__ qw, const float* __restrict__ qb,
    const float* __restrict__ kw, const float* __restrict__ kb,
    const float* __restrict__ vw, const float* __restrict__ vb,
    float* __restrict__ out)
{
    extern __shared__ float sm[];
    float* s_a  = sm;                  // [NPX][CST]
    float* s_kv = sm + NPX * CST;      // [NPX][CST]
    float* s_qw = sm + 2 * NPX * CST;  // [24][24] transposed [ci][co]
    float* s_kw = s_qw + 576;
    float* s_vw = s_kw + 576;
    float* s_qb = s_vw + 576;
    float* s_kb = s_qb + 24;
    float* s_vb = s_kb + 24;

    const int tid = threadIdx.x;
    const int x0 = blockIdx.x * 16, y0 = blockIdx.y * 16;

    // weights (transposed to [ci][co]) + biases
    for (int i = tid; i < 576; i += 256) {
        int co = i % 24, ci = i / 24;
        s_qw[i] = qw[co * 24 + ci];
        s_kw[i] = kw[co * 24 + ci];
        s_vw[i] = vw[co * 24 + ci];
    }
    if (tid < 24) {
        s_qb[tid] = qb[tid];
        s_kb[tid] = kb[tid];
        s_vb[tid] = vb[tid];
    }

    // stage halo'd a tile (zero OOB)
    for (int ci = 0; ci < 24; ci++) {
        const float* ap = a + (long)ci * HW;
        for (int px = tid; px < NPX; px += 256) {
            int hy = px / TS, hx = px % TS;
            int gy = y0 - 3 + hy, gx = x0 - 3 + hx;
            float v = ((unsigned)gy < HGT && (unsigned)gx < WID)
                          ? __ldg(ap + gy * WID + gx) : 0.f;
            s_a[px * CST + ci] = v;
        }
    }
    __syncthreads();

    // ---- K tile into s_kv (OOB -> 0 exactly) ----
    for (int px = tid; px < NPX; px += 256) {
        int hy = px / TS, hx = px % TS;
        int gy = y0 - 3 + hy, gx = x0 - 3 + hx;
        bool ok = ((unsigned)gy < HGT && (unsigned)gx < WID);
        float acc[24];
#pragma unroll
        for (int c = 0; c < 24; c++) acc[c] = s_kb[c];
#pragma unroll
        for (int ci = 0; ci < 24; ci++) {
            float v = s_a[px * CST + ci];
            const float* wp = s_kw + ci * 24;
#pragma unroll
            for (int c = 0; c < 24; c++) acc[c] = fmaf(v, wp[c], acc[c]);
        }
#pragma unroll
        for (int c = 0; c < 24; c++) s_kv[px * CST + c] = ok ? acc[c] : 0.f;
    }

    // ---- Q for own pixel (from b, global; coalesced) ----
    const int ly = tid >> 4, lx = tid & 15;
    const int gy = y0 + ly, gx = x0 + lx;
    const int gidx = gy * WID + gx;

    float q[24];
    {
        float bv[24];
#pragma unroll
        for (int c = 0; c < 24; c++) bv[c] = __ldg(b + (long)c * HW + gidx);
#pragma unroll
        for (int c = 0; c < 24; c++) q[c] = s_qb[c];
#pragma unroll
        for (int ci = 0; ci < 24; ci++) {
            float v = bv[ci];
            const float* wp = s_qw + ci * 24;
#pragma unroll
            for (int c = 0; c < 24; c++) q[c] = fmaf(v, wp[c], q[c]);
        }
    }
    __syncthreads();

    // ---- scores (no bounds checks: halo zero-fill handles OOB) ----
    const int ctr = (ly + 3) * TS + (lx + 3);   // own pixel in halo coords
    const float scale = 0.20412414523193154f;   // 1/sqrt(24)
    float s[49];
#pragma unroll
    for (int p = 0; p < 49; p++) {
        const int np = ctr + (p / 7 - 3) * TS + (p % 7 - 3);
        const float* kp = s_kv + np * CST;
        float d = 0.f;
#pragma unroll
        for (int c = 0; c < 24; c++) d = fmaf(q[c], kp[c], d);
        s[p] = d * scale;
    }

    float m = s[0];
#pragma unroll
    for (int p = 1; p < 49; p++) m = fmaxf(m, s[p]);
    float sum = 0.f;
#pragma unroll
    for (int p = 0; p < 49; p++) {
        s[p] = __expf(s[p] - m);
        sum += s[p];
    }
    const float inv = 1.0f / sum;
    __syncthreads();   // all score reads of s_kv done

    // ---- V tile into s_kv ----
    for (int px = tid; px < NPX; px += 256) {
        int hy = px / TS, hx = px % TS;
        int vgy = y0 - 3 + hy, vgx = x0 - 3 + hx;
        bool ok = ((unsigned)vgy < HGT && (unsigned)vgx < WID);
        float acc[24];
#pragma unroll
        for (int c = 0; c < 24; c++) acc[c] = s_vb[c];
#pragma unroll
        for (int ci = 0; ci < 24; ci++) {
            float v = s_a[px * CST + ci];
            const float* wp = s_vw + ci * 24;
#pragma unroll
            for (int c = 0; c < 24; c++) acc[c] = fmaf(v, wp[c], acc[c]);
        }
#pragma unroll
        for (int c = 0; c < 24; c++) s_kv[px * CST + c] = ok ? acc[c] : 0.f;
    }
    __syncthreads();

    // ---- weighted sum over V ----
    float acc[24];
#pragma unroll
    for (int c = 0; c < 24; c++) acc[c] = 0.f;
#pragma unroll
    for (int p = 0; p < 49; p++) {
        const float wgt = s[p] * inv;
        const int np = ctr + (p / 7 - 3) * TS + (p % 7 - 3);
        const float* vp = s_kv + np * CST;
#pragma unroll
        for (int c = 0; c < 24; c++) acc[c] = fmaf(wgt, vp[c], acc[c]);
    }

    // ---- epilogue: y + a (a from smem center), then b passthrough ----
#pragma unroll
    for (int c = 0; c < 24; c++)
        out[(long)c * HW + gidx] = acc[c] + s_a[ctr * CST + c];
#pragma unroll
    for (int c = 0; c < 24; c++)
        out[(long)(24 + c) * HW + gidx] = __ldg(b + (long)c * HW + gidx);
}

// ---------------------------------------------------------------------------
extern "C" void kernel_launch(void* const* d_in, const int* in_sizes, int n_in,
                              void* d_out, int out_size)
{
    const float* x      = (const float*)d_in[0];
    const float* w0     = (const float*)d_in[1];
    const float* b0     = (const float*)d_in[2];
    const float* w1     = (const float*)d_in[3];
    const float* b1     = (const float*)d_in[4];
    const float* w2     = (const float*)d_in[5];
    const float* b2     = (const float*)d_in[6];
    const float* w3     = (const float*)d_in[7];
    const float* b3     = (const float*)d_in[8];
    const float* skip_w = (const float*)d_in[9];
    const float* skip_b = (const float*)d_in[10];
    const float* q_w    = (const float*)d_in[11];
    const float* q_b    = (const float*)d_in[12];
    const float* k_w    = (const float*)d_in[13];
    const float* k_b    = (const float*)d_in[14];
    const float* v_w    = (const float*)d_in[15];
    const float* v_b    = (const float*)d_in[16];
    float* out = (float*)d_out;

    float *h0, *h1, *ab;
    unsigned* wa;
    cudaGetSymbolAddress((void**)&h0, g_h0);
    cudaGetSymbolAddress((void**)&h1, g_h1);
    cudaGetSymbolAddress((void**)&ab, g_ab);
    cudaGetSymbolAddress((void**)&wa, g_warr);

    arrange_all<<<230, 256>>>(w0, w1, w2, w3, wa);

    const int sm_c0 = 324 * 20 * 4;   // 25920 B
    const int sm_c48 = 324 * 52 * 4;  // 67392 B
    const int sm_attn = (2 * NPX * CST + 3 * 576 + 3 * 24) * 4;  // ~104 KB
    cudaFuncSetAttribute((const void*)conv_mma<3, 8, 48, 1, 3, 20, false>,
                         cudaFuncAttributeMaxDynamicSharedMemorySize, sm_c0);
    cudaFuncSetAttribute((const void*)conv_mma<48, 48, 48, 6, 3, 52, false>,
                         cudaFuncAttributeMaxDynamicSharedMemorySize, sm_c48);
    cudaFuncSetAttribute((const void*)conv_mma<48, 48, 24, 6, 2, 52, true>,
                         cudaFuncAttributeMaxDynamicSharedMemorySize, sm_c48);
    cudaFuncSetAttribute((const void*)attn_fused,
                         cudaFuncAttributeMaxDynamicSharedMemorySize, sm_attn);

    dim3 g(16, 16, 2);
    // conv0: x(3ch) -> h0(48ch), relu
    conv_mma<3, 8, 48, 1, 3, 20, false><<<g, 256, sm_c0>>>(
        x, wa, b0, h0, 3L * HW, 48L * HW, nullptr, nullptr, nullptr);
    // conv1: h0 -> h1
    conv_mma<48, 48, 48, 6, 3, 52, false><<<g, 256, sm_c48>>>(
        h0, wa + 3456, b1, h1, 48L * HW, 48L * HW, nullptr, nullptr, nullptr);
    // conv2: h1 -> h0
    conv_mma<48, 48, 48, 6, 3, 52, false><<<g, 256, sm_c48>>>(
        h1, wa + 24192, b2, h0, 48L * HW, 48L * HW, nullptr, nullptr, nullptr);
    // conv3 + 1x1 skip: h0 -> ab
    conv_mma<48, 48, 24, 6, 2, 52, true><<<g, 256, sm_c48>>>(
        h0, wa + 44928, b3, ab, 48L * HW, 24L * HW, x, skip_w, skip_b);
    // fused qkv + attention + residual + concat
    attn_fused<<<dim3(16, 16), 256, sm_attn>>>(
        ab, ab + 24L * HW, q_w, q_b, k_w, k_b, v_w, v_b, out);
}

// round 10
// speedup vs baseline: 1.0658x; 1.0658x over previous
#include <cuda_runtime.h>
#include <math.h>

#define HW 65536
#define WID 256
#define HGT 256

// Scratch (no allocations allowed)
__device__ float g_h0[2 * 48 * HW];
__device__ float g_h1[2 * 48 * HW];
__device__ float g_ab[2 * 24 * HW];   // batch0 = a, batch1 = b
__device__ float g_Q[24 * HW];
__device__ float g_K[24 * HW];
__device__ float g_V[24 * HW];
__device__ unsigned g_warr[60000];    // fragment-arranged tf32 weights

// ---- tf32 helpers ----------------------------------------------------------
__device__ __forceinline__ unsigned f2tf32(float f) {
    unsigned r;
    asm("cvt.rna.tf32.f32 %0, %1;" : "=r"(r) : "f"(f));
    return r;
}
__device__ __forceinline__ void mma_tf32(float c[4], const unsigned* a,
                                         unsigned b0, unsigned b1) {
    asm("mma.sync.aligned.m16n8k8.row.col.f32.tf32.tf32.f32 "
        "{%0,%1,%2,%3}, {%4,%5,%6,%7}, {%8,%9}, {%0,%1,%2,%3};"
        : "+f"(c[0]), "+f"(c[1]), "+f"(c[2]), "+f"(c[3])
        : "r"(a[0]), "r"(a[1]), "r"(a[2]), "r"(a[3]), "r"(b0), "r"(b1));
}

// ---------------------------------------------------------------------------
// Pre-arrange ALL conv weights into per-lane mma fragment order (one launch).
// Layout in g_warr: conv0 @0 (3456), conv1 @3456 (20736), conv2 @24192
// (20736), conv3 @44928 (13824).  Total 58752.
// ---------------------------------------------------------------------------
__global__ void arrange_all(const float* __restrict__ w0,
                            const float* __restrict__ w1,
                            const float* __restrict__ w2,
                            const float* __restrict__ w3,
                            unsigned* __restrict__ dst)
{
    int idx = blockIdx.x * 256 + threadIdx.x;
    if (idx >= 58752) return;
    const float* w;
    int CIN, COUT, KSTEPS, MF, base;
    if (idx < 3456)       { w = w0; CIN = 3;  COUT = 48; KSTEPS = 1; MF = 3; base = 0; }
    else if (idx < 24192) { w = w1; CIN = 48; COUT = 48; KSTEPS = 6; MF = 3; base = 3456; }
    else if (idx < 44928) { w = w2; CIN = 48; COUT = 48; KSTEPS = 6; MF = 3; base = 24192; }
    else                  { w = w3; CIN = 48; COUT = 24; KSTEPS = 6; MF = 2; base = 44928; }
    int i    = idx - base;
    int j    = i & 3;
    int lane = (i >> 2) & 31;
    int rest = i >> 7;               // (tap*KSTEPS+s)*MF+mf
    int mf   = rest % MF;
    int ts   = rest / MF;
    int s    = ts % KSTEPS;
    int tap  = ts / KSTEPS;
    int cout = 16 * mf + (lane >> 2) + ((j & 1) << 3);
    int ci   = 8 * s + (lane & 3) + ((j & 2) << 1);
    float v = (cout < COUT && ci < CIN) ? w[(cout * CIN + ci) * 9 + tap] : 0.f;
    dst[idx] = f2tf32(v);
}

// ---------------------------------------------------------------------------
// Tensor-core 3x3 conv (implicit GEMM, tf32 mma.sync).
// ci columns PERMUTED within each 8-group (0,4,1,5,2,6,3,7) so a lane's
// (b0,b1) = (k=t4, k=t4+4) pair is one LDS.64.
// ---------------------------------------------------------------------------
template <int CIN, int CIN_STAGE, int COUT, int KSTEPS, int MF, int CIP, bool SKIP>
__global__ void __launch_bounds__(256, 2) conv_mma(
    const float* __restrict__ in, const unsigned* __restrict__ warr,
    const float* __restrict__ bias, float* __restrict__ out,
    long in_bs, long out_bs,
    const float* __restrict__ skip_in, const float* __restrict__ skip_w,
    const float* __restrict__ skip_b)
{
    extern __shared__ unsigned s_in[];   // [18*18][CIP] tf32, ci permuted
    const int tid = threadIdx.x;
    const int batch = blockIdx.z;
    in  += (long)batch * in_bs;
    out += (long)batch * out_bs;
    const int x0 = blockIdx.x * 16, y0 = blockIdx.y * 16;

    for (int idx = tid; idx < 324 * CIN_STAGE; idx += 256) {
        int ci = idx / 324, rc = idx % 324;
        int r = rc / 18, c = rc % 18;
        int gy = y0 - 1 + r, gx = x0 - 1 + c;
        float v = 0.f;
        if (ci < CIN && (unsigned)gy < HGT && (unsigned)gx < WID)
            v = in[(long)ci * HW + gy * WID + gx];
        // permuted column: within 8-group, (ci&3)*2 + ((ci>>2)&1)
        int col = (ci & ~7) + ((ci & 3) << 1) + ((ci >> 2) & 1);
        s_in[rc * CIP + col] = f2tf32(v);
    }
    __syncthreads();

    const int w = tid >> 5, lane = tid & 31;
    const int q = lane >> 2, t4 = lane & 3;

    float acc[MF][4][4];
#pragma unroll
    for (int mf = 0; mf < MF; mf++)
#pragma unroll
        for (int nf = 0; nf < 4; nf++)
#pragma unroll
            for (int j = 0; j < 4; j++) acc[mf][nf][j] = 0.f;

    // per-nfrag base address: pixel (y_n, x_n), +1 halo origin, + 2*t4 (pair)
    int base[4];
#pragma unroll
    for (int nf = 0; nf < 4; nf++) {
        int yn = 2 * w + (nf >> 1);
        int xn = 8 * (nf & 1) + q;
        base[nf] = ((yn + 1) * 18 + (xn + 1)) * CIP + 2 * t4;
    }
    const uint4* wp = (const uint4*)warr + lane;

#pragma unroll
    for (int tap = 0; tap < 9; tap++) {
        const int dy = tap / 3 - 1, dx = tap % 3 - 1;
        const int off = (dy * 18 + dx) * CIP;
#pragma unroll
        for (int s = 0; s < KSTEPS; s++) {
            uint4 a[MF];
#pragma unroll
            for (int mf = 0; mf < MF; mf++)
                a[mf] = wp[((tap * KSTEPS + s) * MF + mf) * 32];
#pragma unroll
            for (int nf = 0; nf < 4; nf++) {
                uint2 b = *(const uint2*)(s_in + base[nf] + off + 8 * s);
#pragma unroll
                for (int mf = 0; mf < MF; mf++)
                    mma_tf32(acc[mf][nf], (const unsigned*)&a[mf], b.x, b.y);
            }
        }
    }

    // Epilogue: bias + relu (+1x1 skip), write fp32 NCHW.
#pragma unroll
    for (int mf = 0; mf < MF; mf++) {
        const int coutL = 16 * mf + q;
        const int coutH = coutL + 8;
        const float bL = (coutL < COUT) ? __ldg(bias + coutL) : 0.f;
        const float bH = (coutH < COUT) ? __ldg(bias + coutH) : 0.f;
#pragma unroll
        for (int nf = 0; nf < 4; nf++) {
            const int gy = y0 + 2 * w + (nf >> 1);
            const int gx = x0 + 8 * (nf & 1) + 2 * t4;
            const int o = gy * WID + gx;
            float v0 = fmaxf(acc[mf][nf][0] + bL, 0.f);
            float v1 = fmaxf(acc[mf][nf][1] + bL, 0.f);
            float v2 = fmaxf(acc[mf][nf][2] + bH, 0.f);
            float v3 = fmaxf(acc[mf][nf][3] + bH, 0.f);
            if (SKIP) {
                const float* xp = skip_in + (long)batch * 3 * HW;
                float xa0 = __ldg(xp + o),          xb0 = __ldg(xp + o + 1);
                float xa1 = __ldg(xp + HW + o),     xb1 = __ldg(xp + HW + o + 1);
                float xa2 = __ldg(xp + 2 * HW + o), xb2 = __ldg(xp + 2 * HW + o + 1);
                if (coutL < COUT) {
                    float sb = __ldg(skip_b + coutL);
                    float w0 = __ldg(skip_w + coutL * 3);
                    float w1 = __ldg(skip_w + coutL * 3 + 1);
                    float w2 = __ldg(skip_w + coutL * 3 + 2);
                    v0 += sb + xa0 * w0 + xa1 * w1 + xa2 * w2;
                    v1 += sb + xb0 * w0 + xb1 * w1 + xb2 * w2;
                    *(float2*)(out + (long)coutL * HW + o) = make_float2(v0, v1);
                }
                if (coutH < COUT) {
                    float sb = __ldg(skip_b + coutH);
                    float w0 = __ldg(skip_w + coutH * 3);
                    float w1 = __ldg(skip_w + coutH * 3 + 1);
                    float w2 = __ldg(skip_w + coutH * 3 + 2);
                    v2 += sb + xa0 * w0 + xa1 * w1 + xa2 * w2;
                    v3 += sb + xb0 * w0 + xb1 * w1 + xb2 * w2;
                    *(float2*)(out + (long)coutH * HW + o) = make_float2(v2, v3);
                }
            } else {
                *(float2*)(out + (long)coutL * HW + o) = make_float2(v0, v1);
                *(float2*)(out + (long)coutH * HW + o) = make_float2(v2, v3);
            }
        }
    }
}

// ---------------------------------------------------------------------------
// Fused 1x1 convs: K = kw*a, V = vw*a, Q = qw*b. One thread per pixel.
// ---------------------------------------------------------------------------
__global__ void __launch_bounds__(256) qkv_kernel(
    const float* __restrict__ a, const float* __restrict__ b,
    const float* __restrict__ qw, const float* __restrict__ qb,
    const float* __restrict__ kw, const float* __restrict__ kb,
    const float* __restrict__ vw, const float* __restrict__ vb,
    float* __restrict__ Q, float* __restrict__ K, float* __restrict__ V)
{
    __shared__ float s_qw[576], s_kw[576], s_vw[576];
    __shared__ float s_qb[24], s_kb[24], s_vb[24];
    for (int i = threadIdx.x; i < 576; i += 256) {
        int co = i % 24, ci = i / 24;
        s_qw[i] = qw[co * 24 + ci];
        s_kw[i] = kw[co * 24 + ci];
        s_vw[i] = vw[co * 24 + ci];
    }
    if (threadIdx.x < 24) {
        s_qb[threadIdx.x] = qb[threadIdx.x];
        s_kb[threadIdx.x] = kb[threadIdx.x];
        s_vb[threadIdx.x] = vb[threadIdx.x];
    }
    __syncthreads();

    const int idx = blockIdx.x * 256 + threadIdx.x;

    float iv[24];
#pragma unroll
    for (int c = 0; c < 24; c++) iv[c] = a[c * HW + idx];

    float acc[24];
#pragma unroll
    for (int c = 0; c < 24; c++) acc[c] = s_kb[c];
#pragma unroll
    for (int ci = 0; ci < 24; ci++) {
        float v = iv[ci];
        const float* wp = s_kw + ci * 24;
#pragma unroll
        for (int c = 0; c < 24; c++) acc[c] = fmaf(v, wp[c], acc[c]);
    }
#pragma unroll
    for (int c = 0; c < 24; c++) K[c * HW + idx] = acc[c];

#pragma unroll
    for (int c = 0; c < 24; c++) acc[c] = s_vb[c];
#pragma unroll
    for (int ci = 0; ci < 24; ci++) {
        float v = iv[ci];
        const float* wp = s_vw + ci * 24;
#pragma unroll
        for (int c = 0; c < 24; c++) acc[c] = fmaf(v, wp[c], acc[c]);
    }
#pragma unroll
    for (int c = 0; c < 24; c++) V[c * HW + idx] = acc[c];

#pragma unroll
    for (int c = 0; c < 24; c++) iv[c] = b[c * HW + idx];
#pragma unroll
    for (int c = 0; c < 24; c++) acc[c] = s_qb[c];
#pragma unroll
    for (int ci = 0; ci < 24; ci++) {
        float v = iv[ci];
        const float* wp = s_qw + ci * 24;
#pragma unroll
        for (int c = 0; c < 24; c++) acc[c] = fmaf(v, wp[c], acc[c]);
    }
#pragma unroll
    for (int c = 0; c < 24; c++) Q[c * HW + idx] = acc[c];
}

// ---------------------------------------------------------------------------
// Local 7x7 attention (pad 3, zero-padded unfold => OOB score = 0, included
// in softmax; OOB V = 0). out[0:24] = y + a, out[24:48] = b.
// ---------------------------------------------------------------------------
__global__ void __launch_bounds__(256) attn_kernel(
    const float* __restrict__ Q, const float* __restrict__ K,
    const float* __restrict__ Vv, const float* __restrict__ a,
    const float* __restrict__ b, float* __restrict__ out)
{
    const int idx = blockIdx.x * 256 + threadIdx.x;
    const int y = idx >> 8;
    const int x = idx & 255;

    float q[24];
#pragma unroll
    for (int c = 0; c < 24; c++) q[c] = Q[c * HW + idx];

    const float scale = 0.20412414523193154f;  // 1/sqrt(24)
    float s[49];
#pragma unroll
    for (int p = 0; p < 49; p++) {
        const int ny = y + p / 7 - 3;
        const int nx = x + p % 7 - 3;
        float d = 0.f;
        if ((unsigned)ny < HGT && (unsigned)nx < WID) {
            const float* kp = K + ny * WID + nx;
#pragma unroll
            for (int c = 0; c < 24; c++) d = fmaf(q[c], __ldg(kp + c * HW), d);
        }
        s[p] = d * scale;
    }

    float m = s[0];
#pragma unroll
    for (int p = 1; p < 49; p++) m = fmaxf(m, s[p]);
    float sum = 0.f;
#pragma unroll
    for (int p = 0; p < 49; p++) {
        s[p] = __expf(s[p] - m);
        sum += s[p];
    }
    const float inv = 1.0f / sum;

    float acc[24];
#pragma unroll
    for (int c = 0; c < 24; c++) acc[c] = 0.f;
#pragma unroll
    for (int p = 0; p < 49; p++) {
        const int ny = y + p / 7 - 3;
        const int nx = x + p % 7 - 3;
        if ((unsigned)ny < HGT && (unsigned)nx < WID) {
            const float wgt = s[p] * inv;
            const float* vp = Vv + ny * WID + nx;
#pragma unroll
            for (int c = 0; c < 24; c++) acc[c] = fmaf(wgt, __ldg(vp + c * HW), acc[c]);
        }
    }

#pragma unroll
    for (int c = 0; c < 24; c++) out[c * HW + idx] = acc[c] + a[c * HW + idx];
#pragma unroll
    for (int c = 0; c < 24; c++) out[(24 + c) * HW + idx] = b[c * HW + idx];
}

// ---------------------------------------------------------------------------
extern "C" void kernel_launch(void* const* d_in, const int* in_sizes, int n_in,
                              void* d_out, int out_size)
{
    const float* x      = (const float*)d_in[0];
    const float* w0     = (const float*)d_in[1];
    const float* b0     = (const float*)d_in[2];
    const float* w1     = (const float*)d_in[3];
    const float* b1     = (const float*)d_in[4];
    const float* w2     = (const float*)d_in[5];
    const float* b2     = (const float*)d_in[6];
    const float* w3     = (const float*)d_in[7];
    const float* b3     = (const float*)d_in[8];
    const float* skip_w = (const float*)d_in[9];
    const float* skip_b = (const float*)d_in[10];
    const float* q_w    = (const float*)d_in[11];
    const float* q_b    = (const float*)d_in[12];
    const float* k_w    = (const float*)d_in[13];
    const float* k_b    = (const float*)d_in[14];
    const float* v_w    = (const float*)d_in[15];
    const float* v_b    = (const float*)d_in[16];
    float* out = (float*)d_out;

    float *h0, *h1, *ab, *Qp, *Kp, *Vp;
    unsigned* wa;
    cudaGetSymbolAddress((void**)&h0, g_h0);
    cudaGetSymbolAddress((void**)&h1, g_h1);
    cudaGetSymbolAddress((void**)&ab, g_ab);
    cudaGetSymbolAddress((void**)&Qp, g_Q);
    cudaGetSymbolAddress((void**)&Kp, g_K);
    cudaGetSymbolAddress((void**)&Vp, g_V);
    cudaGetSymbolAddress((void**)&wa, g_warr);

    arrange_all<<<230, 256>>>(w0, w1, w2, w3, wa);

    const int sm_c0 = 324 * 20 * 4;   // 25920 B
    const int sm_c48 = 324 * 52 * 4;  // 67392 B
    cudaFuncSetAttribute((const void*)conv_mma<3, 8, 48, 1, 3, 20, false>,
                         cudaFuncAttributeMaxDynamicSharedMemorySize, sm_c0);
    cudaFuncSetAttribute((const void*)conv_mma<48, 48, 48, 6, 3, 52, false>,
                         cudaFuncAttributeMaxDynamicSharedMemorySize, sm_c48);
    cudaFuncSetAttribute((const void*)conv_mma<48, 48, 24, 6, 2, 52, true>,
                         cudaFuncAttributeMaxDynamicSharedMemorySize, sm_c48);

    dim3 g(16, 16, 2);
    // conv0: x(3ch) -> h0(48ch), relu
    conv_mma<3, 8, 48, 1, 3, 20, false><<<g, 256, sm_c0>>>(
        x, wa, b0, h0, 3L * HW, 48L * HW, nullptr, nullptr, nullptr);
    // conv1: h0 -> h1
    conv_mma<48, 48, 48, 6, 3, 52, false><<<g, 256, sm_c48>>>(
        h0, wa + 3456, b1, h1, 48L * HW, 48L * HW, nullptr, nullptr, nullptr);
    // conv2: h1 -> h0
    conv_mma<48, 48, 48, 6, 3, 52, false><<<g, 256, sm_c48>>>(
        h1, wa + 24192, b2, h0, 48L * HW, 48L * HW, nullptr, nullptr, nullptr);
    // conv3 + 1x1 skip: h0 -> ab
    conv_mma<48, 48, 24, 6, 2, 52, true><<<g, 256, sm_c48>>>(
        h0, wa + 44928, b3, ab, 48L * HW, 24L * HW, x, skip_w, skip_b);
    // Q/K/V 1x1 convs
    qkv_kernel<<<HW / 256, 256>>>(ab, ab + 24L * HW, q_w, q_b, k_w, k_b,
                                  v_w, v_b, Qp, Kp, Vp);
    // attention + residual + concat
    attn_kernel<<<HW / 256, 256>>>(Qp, Kp, Vp, ab, ab + 24L * HW, out);
}